// round 15
// baseline (speedup 1.0000x reference)
#include <cuda_runtime.h>
#include <cuda_fp16.h>
#include <cstdint>

// ---------------------------------------------------------------------------
// Problem constants
// ---------------------------------------------------------------------------
#define BS    64
#define CIN   128
#define COUT  128
#define HH    56
#define WW    56
#define PADW  58
#define VROWS (PADW*PADW)   // 3364 meaningful padded-raster rows
#define NR2   3584          // allocated rows per sample (zero tail)
#define RTPS  (NR2/32)      // 112 row-tiles per sample
#define MT    27            // conv m-tiles of 128 per sample
#define KCH   18            // 9 taps x 2 cin-chunks of 64
#define STAGE_BYTES 32768   // A tile 16KB + B tile 16KB
#define SMEM_TOTAL  (3*STAGE_BYTES)   // 96 KB

#define MBLOCKS (COUT*9)      // 1152 mix blocks
#define PERB    (RTPS + MT)   // 139 blocks per sample (transform + conv)
#define GRID_TOTAL (MBLOCKS + BS*PERB)   // 10048

// ---------------------------------------------------------------------------
// Scratch + dependency flags (device globals; no runtime allocation)
// ---------------------------------------------------------------------------
__device__ __half g_xt[(size_t)BS * NR2 * CIN];          // 58.7 MB
__device__ __half g_wt[(size_t)BS * 9 * COUT * CIN];     // 18.9 MB
__device__ float  g_bmix[BS * COUT];
__device__ int    g_tdone[BS];
__device__ int    g_mdone;

// ---------------------------------------------------------------------------
// PTX helpers
// ---------------------------------------------------------------------------
__device__ __forceinline__ uint32_t smem_u32(const void* p) {
    uint32_t a;
    asm("{ .reg .u64 t; cvta.to.shared.u64 t, %1; cvt.u32.u64 %0, t; }"
        : "=r"(a) : "l"(p));
    return a;
}
__device__ __forceinline__ void cp16(uint32_t dst, const void* src) {
    asm volatile("cp.async.cg.shared.global [%0], [%1], 16;"
                 :: "r"(dst), "l"(__cvta_generic_to_global(src)) : "memory");
}
__device__ __forceinline__ void cp_commit() {
    asm volatile("cp.async.commit_group;" ::: "memory");
}
template <int N>
__device__ __forceinline__ void cp_wait() {
    asm volatile("cp.async.wait_group %0;" :: "n"(N) : "memory");
}
__device__ __forceinline__ void ldsm4(uint32_t* r, uint32_t addr) {
    asm volatile("ldmatrix.sync.aligned.m8n8.x4.shared.b16 {%0,%1,%2,%3}, [%4];"
                 : "=r"(r[0]), "=r"(r[1]), "=r"(r[2]), "=r"(r[3]) : "r"(addr));
}
__device__ __forceinline__ void mma16816(float* c, const uint32_t* a, const uint32_t* b) {
    asm volatile(
        "mma.sync.aligned.m16n8k16.row.col.f32.f16.f16.f32 "
        "{%0,%1,%2,%3}, {%4,%5,%6,%7}, {%8,%9}, {%0,%1,%2,%3};"
        : "+f"(c[0]), "+f"(c[1]), "+f"(c[2]), "+f"(c[3])
        : "r"(a[0]), "r"(a[1]), "r"(a[2]), "r"(a[3]), "r"(b[0]), "r"(b[1]));
}

// ---------------------------------------------------------------------------
// Kernel 0: reset dependency flags (each graph replay).
// ---------------------------------------------------------------------------
__global__ void reset_kernel()
{
    const int i = threadIdx.x;
    if (i < BS) g_tdone[i] = 0;
    if (i == BS) g_mdone = 0;
}

// ---------------------------------------------------------------------------
// Kernel 1 (fused everything): CTA order
//   [0, MBLOCKS)                  : mix (w_mix fp16 + bias)   -> g_mdone++
//   then per sample b:
//     [base, base+112)            : transform tiles of b      -> g_tdone[b]++
//     [base+112, base+139)        : conv m-tiles of b (spin-wait on flags)
// Forward progress: conv CTAs only spin on strictly earlier bids.
// ---------------------------------------------------------------------------
__global__ __launch_bounds__(256, 2)
void fused_kernel(const float* __restrict__ x,
                  const float* __restrict__ routing,   // [BS, 8]
                  const float* __restrict__ weight,    // [8, COUT, CIN, 3,3]
                  const float* __restrict__ bias,      // [8, COUT]
                  float* __restrict__ out)
{
    extern __shared__ char smem[];
    const int blk = blockIdx.x;
    const int tid = threadIdx.x;

    if (blk < MBLOCKS) {
        // ================= MIX =================
        const int oc = blk & 127;
        const int f  = blk >> 7;             // 0..8
        float* r_s = (float*)smem;           // [64][8]
        float* w_s = r_s + 512;              // [8][128]

        for (int i = tid; i < 64 * 8; i += 256)
            r_s[i] = routing[i];
        for (int i = tid; i < 8 * 128; i += 256) {
            const int k = i >> 7, c = i & 127;
            w_s[k * 128 + c] = weight[(((size_t)k * COUT + oc) * CIN + c) * 9 + f];
        }
        __syncthreads();

        const int warp = tid >> 5, lane = tid & 31;
        const int c0 = lane * 4;
#pragma unroll
        for (int bi = 0; bi < 8; bi++) {
            const int b = warp + bi * 8;
            const float* rb = r_s + b * 8;
            float s0 = 0.f, s1 = 0.f, s2 = 0.f, s3 = 0.f;
#pragma unroll
            for (int k = 0; k < 8; k++) {
                const float r = rb[k];
                s0 += r * w_s[k * 128 + c0];
                s1 += r * w_s[k * 128 + c0 + 1];
                s2 += r * w_s[k * 128 + c0 + 2];
                s3 += r * w_s[k * 128 + c0 + 3];
            }
            __half h[4];
            h[0] = __float2half(s0); h[1] = __float2half(s1);
            h[2] = __float2half(s2); h[3] = __float2half(s3);
            *(uint2*)&g_wt[(((size_t)b * 9 + f) * COUT + oc) * CIN + c0] = *(const uint2*)h;
        }
        if (f == 0 && tid < 64) {
            float sb = 0.f;
#pragma unroll
            for (int k = 0; k < 8; k++)
                sb += r_s[tid * 8 + k] * bias[k * COUT + oc];
            g_bmix[tid * COUT + oc] = sb;
        }
        __threadfence();
        __syncthreads();
        if (tid == 0) atomicAdd(&g_mdone, 1);
        return;
    }

    const int i1 = blk - MBLOCKS;
    const int b  = i1 / PERB;
    const int j  = i1 - b * PERB;

    if (j < RTPS) {
        // ================= TRANSFORM tile j of sample b =================
        float (*s)[33] = (float(*)[33])smem;   // [128][33]
        const int r0 = j * 32;
        const int warp = tid >> 5, lane = tid & 31;
        {
            const int r = r0 + lane;
            const int hp = r / PADW, wp = r - hp * PADW;
            const bool ok = (r < VROWS) && (hp >= 1) && (hp < 57) && (wp >= 1) && (wp < 57);
            const int off = ok ? ((hp - 1) * WW + (wp - 1)) : 0;
            const float* xr = x + (size_t)b * CIN * (HH * WW) + off;
#pragma unroll
            for (int k = 0; k < 16; k++) {
                const int c = warp + k * 8;
                const float v = xr[(size_t)c * (HH * WW)];
                s[c][lane] = ok ? v : 0.f;
            }
        }
        __syncthreads();
#pragma unroll
        for (int i = tid; i < 32 * 16; i += 256) {
            const int rr = i >> 4;
            const int c0 = (i & 15) * 8;
            __half h[8];
#pragma unroll
            for (int jj = 0; jj < 8; jj++)
                h[jj] = __float2half(s[c0 + jj][rr]);
            *(uint4*)&g_xt[((size_t)b * NR2 + r0 + rr) * CIN + c0] = *(const uint4*)h;
        }
        __threadfence();
        __syncthreads();
        if (tid == 0) atomicAdd(&g_tdone[b], 1);
        return;
    }

    // ================= CONV m-tile (j - RTPS) of sample b =================
    // Wait for mix (all) + transform (this sample). Producers are earlier bids.
    if (tid == 0) {
        volatile int* vm = &g_mdone;
        volatile int* vt = &g_tdone[b];
        while (*vm < MBLOCKS) __nanosleep(64);
        while (*vt < RTPS)    __nanosleep(64);
    }
    __syncthreads();
    __threadfence();

    const uint32_t sbase = smem_u32(smem);
    const int wid  = tid >> 5;
    const int lane = tid & 31;
    const int m_base = (j - RTPS) * 128;

    const int wm = (wid >> 2) * 64;          // warp m offset (2 groups)
    const int wn = (wid & 3) * 32;           // warp n offset (4 groups)
    const int gid = lane >> 2, tig = lane & 3;

    const __half* xt = g_xt + (size_t)b * NR2 * CIN;
    const __half* wt = g_wt + (size_t)b * 9 * COUT * CIN;

    float c[4][4][4];
#pragma unroll
    for (int mi = 0; mi < 4; mi++)
#pragma unroll
        for (int ni = 0; ni < 4; ni++)
#pragma unroll
            for (int k = 0; k < 4; k++) c[mi][ni][k] = 0.f;

    const int lr = tid >> 3, lj = tid & 7;

    auto load_stage = [&](int g, int s) {
        int f = g >> 1, cc = (g & 1) * 64;
        int shift = (f / 3) * PADW + (f % 3);
        const __half* gA = xt + ((size_t)(m_base + shift)) * CIN + cc;
        const __half* gB = wt + ((size_t)f * COUT) * CIN + cc;
        uint32_t sA = sbase + s * STAGE_BYTES;
        uint32_t sB = sA + 16384;
#pragma unroll
        for (int it = 0; it < 4; it++) {
            int row = lr + it * 32;
            uint32_t dchunk = (uint32_t)(lj ^ (row & 7));
            cp16(sA + row * 128 + dchunk * 16, gA + (size_t)row * CIN + lj * 8);
            cp16(sB + row * 128 + dchunk * 16, gB + (size_t)row * CIN + lj * 8);
        }
        cp_commit();
    };

    load_stage(0, 0);
    load_stage(1, 1);

    const int x7 = lane & 7;
    const int a_row = wm + (lane & 15);
    const int a_cbase = lane >> 4;
    const int b_row = wn + ((lane >> 4) << 3) + (lane & 7);
    const int b_cbase = (lane >> 3) & 1;

#pragma unroll
    for (int g = 0; g < KCH; g++) {
        if (g < KCH - 1) cp_wait<1>(); else cp_wait<0>();
        __syncthreads();
        if (g + 2 < KCH) load_stage(g + 2, (g + 2) % 3);

        const int s = g % 3;                 // compile-time after unroll
        const uint32_t sA = sbase + s * STAGE_BYTES;
        const uint32_t sB = sA + 16384;
        const uint32_t baseA = sA + (uint32_t)a_row * 128;
        const uint32_t baseB = sB + (uint32_t)b_row * 128;

#pragma unroll
        for (int ks = 0; ks < 4; ks++) {
            uint32_t a[4][4], bb[2][4];
#pragma unroll
            for (int mi = 0; mi < 4; mi++) {
                uint32_t ch = (uint32_t)((ks * 2 + a_cbase) ^ x7);
                ldsm4(a[mi], baseA + mi * 16 * 128 + ch * 16);
            }
#pragma unroll
            for (int nj = 0; nj < 2; nj++) {
                uint32_t ch = (uint32_t)((ks * 2 + b_cbase) ^ x7);
                ldsm4(bb[nj], baseB + nj * 16 * 128 + ch * 16);
            }
#pragma unroll
            for (int mi = 0; mi < 4; mi++)
#pragma unroll
                for (int ni = 0; ni < 4; ni++)
                    mma16816(c[mi][ni], a[mi], &bb[ni >> 1][(ni & 1) * 2]);
        }
    }

    // ---------------- epilogue: direct fragment -> gmem stores ----------
    const float* bm = g_bmix + b * COUT;
    float* ob = out + (size_t)b * COUT * (HH * WW);
#pragma unroll
    for (int ni = 0; ni < 4; ni++) {
        const int oc = wn + ni * 8 + 2 * tig;
        const float bv0 = __ldg(&bm[oc]);
        const float bv1 = __ldg(&bm[oc + 1]);
        float* o0 = ob + (size_t)oc * (HH * WW);
        float* o1 = o0 + (HH * WW);
#pragma unroll
        for (int mi = 0; mi < 4; mi++) {
            const int p0 = m_base + wm + mi * 16 + gid;
            const int p1 = p0 + 8;
            const int h0 = p0 / PADW, w0 = p0 - h0 * PADW;
            const int h1 = p1 / PADW, w1 = p1 - h1 * PADW;
            if (w0 < WW && h0 < HH) {
                o0[h0 * WW + w0] = c[mi][ni][0] + bv0;
                o1[h0 * WW + w0] = c[mi][ni][1] + bv1;
            }
            if (w1 < WW && h1 < HH) {
                o0[h1 * WW + w1] = c[mi][ni][2] + bv0;
                o1[h1 * WW + w1] = c[mi][ni][3] + bv1;
            }
        }
    }
}

// ---------------------------------------------------------------------------
extern "C" void kernel_launch(void* const* d_in, const int* in_sizes, int n_in,
                              void* d_out, int out_size)
{
    const float* x       = (const float*)d_in[0];   // [64,128,56,56]
    const float* routing = (const float*)d_in[1];   // [64,8]
    const float* weight  = (const float*)d_in[2];   // [8,128,128,3,3]
    const float* bias    = (const float*)d_in[3];   // [8,128]
    float* out           = (float*)d_out;           // [64,128,56,56]

    static int attr_set = 0;
    if (!attr_set) {
        cudaFuncSetAttribute(fused_kernel,
                             cudaFuncAttributeMaxDynamicSharedMemorySize, SMEM_TOTAL);
        attr_set = 1;
    }

    reset_kernel<<<1, 128>>>();
    fused_kernel<<<GRID_TOTAL, 256, SMEM_TOTAL>>>(x, routing, weight, bias, out);
}

// round 16
// speedup vs baseline: 1.1157x; 1.1157x over previous
#include <cuda_runtime.h>
#include <cuda_fp16.h>
#include <cstdint>

// ---------------------------------------------------------------------------
// Problem constants
// ---------------------------------------------------------------------------
#define BS    64
#define CIN   128
#define COUT  128
#define HH    56
#define WW    56
#define PADW  58
#define VROWS (PADW*PADW)   // 3364 meaningful padded-raster rows
#define NR2   3584          // allocated rows per sample (zero tail)
#define RTPS  (NR2/32)      // 112 row-tiles per sample
#define MT    27            // conv m-tiles of 128 per sample
#define KCH   18            // 9 taps x 2 cin-chunks of 64
#define STAGE_BYTES 32768   // A tile 16KB + B tile 16KB
#define SMEM_TOTAL  (3*STAGE_BYTES)   // 96 KB

#define MBLOCKS (COUT*9)    // 1152 mix blocks
#define LAG     3
// order: [mix][T0..T2][ (C(g),T(g+3)) g=0..60 ][C61..C63]
#define HEAD_T   (LAG*RTPS)            // 336
#define FULL_G   (BS - LAG)            // 61 groups of (27 C + 112 T)
#define GRID_TOTAL (MBLOCKS + HEAD_T + FULL_G*(MT+RTPS) + LAG*MT)  // 10048

// ---------------------------------------------------------------------------
// Scratch + dependency flags (device globals; no runtime allocation)
// ---------------------------------------------------------------------------
__device__ __half g_xt[(size_t)BS * NR2 * CIN];          // 58.7 MB
__device__ __half g_wt[(size_t)BS * 9 * COUT * CIN];     // 18.9 MB
__device__ float  g_bmix[BS * COUT];
__device__ int    g_tdone[BS];
__device__ int    g_mdone;

// ---------------------------------------------------------------------------
// PTX helpers
// ---------------------------------------------------------------------------
__device__ __forceinline__ uint32_t smem_u32(const void* p) {
    uint32_t a;
    asm("{ .reg .u64 t; cvta.to.shared.u64 t, %1; cvt.u32.u64 %0, t; }"
        : "=r"(a) : "l"(p));
    return a;
}
__device__ __forceinline__ void cp16(uint32_t dst, const void* src) {
    asm volatile("cp.async.cg.shared.global [%0], [%1], 16;"
                 :: "r"(dst), "l"(__cvta_generic_to_global(src)) : "memory");
}
__device__ __forceinline__ void cp_commit() {
    asm volatile("cp.async.commit_group;" ::: "memory");
}
template <int N>
__device__ __forceinline__ void cp_wait() {
    asm volatile("cp.async.wait_group %0;" :: "n"(N) : "memory");
}
__device__ __forceinline__ void ldsm4(uint32_t* r, uint32_t addr) {
    asm volatile("ldmatrix.sync.aligned.m8n8.x4.shared.b16 {%0,%1,%2,%3}, [%4];"
                 : "=r"(r[0]), "=r"(r[1]), "=r"(r[2]), "=r"(r[3]) : "r"(addr));
}
__device__ __forceinline__ void mma16816(float* c, const uint32_t* a, const uint32_t* b) {
    asm volatile(
        "mma.sync.aligned.m16n8k16.row.col.f32.f16.f16.f32 "
        "{%0,%1,%2,%3}, {%4,%5,%6,%7}, {%8,%9}, {%0,%1,%2,%3};"
        : "+f"(c[0]), "+f"(c[1]), "+f"(c[2]), "+f"(c[3])
        : "r"(a[0]), "r"(a[1]), "r"(a[2]), "r"(a[3]), "r"(b[0]), "r"(b[1]));
}

// ---------------------------------------------------------------------------
// Kernel 0: reset dependency flags (each graph replay).
// ---------------------------------------------------------------------------
__global__ void reset_kernel()
{
    const int i = threadIdx.x;
    if (i < BS) g_tdone[i] = 0;
    if (i == BS) g_mdone = 0;
}

// ---------------------------------------------------------------------------
// Kernel 1 (fused, lag-3 interleave):
//   [0,1152)        mix            -> g_mdone++
//   [1152,1488)     T(b=0..2)
//   61 groups       C(g) then T(g+3)   (conv spin-waits; producers are
//                                       >=251 bids earlier -> spin ~0)
//   tail            C(61..63)
// ---------------------------------------------------------------------------
__global__ __launch_bounds__(256, 2)
void fused_kernel(const float* __restrict__ x,
                  const float* __restrict__ routing,   // [BS, 8]
                  const float* __restrict__ weight,    // [8, COUT, CIN, 3,3]
                  const float* __restrict__ bias,      // [8, COUT]
                  float* __restrict__ out)
{
    extern __shared__ char smem[];
    const int blk = blockIdx.x;
    const int tid = threadIdx.x;

    // ---------------- decode block role ----------------
    int role;            // 0=mix, 1=transform, 2=conv
    int rb = 0, rj = 0;  // sample, tile index
    if (blk < MBLOCKS) {
        role = 0;
    } else {
        int i2 = blk - MBLOCKS;
        if (i2 < HEAD_T) {
            role = 1; rb = i2 / RTPS; rj = i2 - rb * RTPS;
        } else {
            int i3 = i2 - HEAD_T;
            if (i3 < FULL_G * (MT + RTPS)) {
                int g = i3 / (MT + RTPS);
                int r = i3 - g * (MT + RTPS);
                if (r < MT) { role = 2; rb = g; rj = r; }
                else        { role = 1; rb = g + LAG; rj = r - MT; }
            } else {
                int i4 = i3 - FULL_G * (MT + RTPS);
                role = 2; rb = FULL_G + i4 / MT; rj = i4 % MT;
            }
        }
    }

    if (role == 0) {
        // ================= MIX =================
        const int oc = blk & 127;
        const int f  = blk >> 7;             // 0..8
        float* r_s = (float*)smem;           // [64][8]
        float* w_s = r_s + 512;              // [8][128]

        for (int i = tid; i < 64 * 8; i += 256)
            r_s[i] = routing[i];
        for (int i = tid; i < 8 * 128; i += 256) {
            const int k = i >> 7, c = i & 127;
            w_s[k * 128 + c] = weight[(((size_t)k * COUT + oc) * CIN + c) * 9 + f];
        }
        __syncthreads();

        const int warp = tid >> 5, lane = tid & 31;
        const int c0 = lane * 4;
#pragma unroll
        for (int bi = 0; bi < 8; bi++) {
            const int b = warp + bi * 8;
            const float* rbp = r_s + b * 8;
            float s0 = 0.f, s1 = 0.f, s2 = 0.f, s3 = 0.f;
#pragma unroll
            for (int k = 0; k < 8; k++) {
                const float r = rbp[k];
                s0 += r * w_s[k * 128 + c0];
                s1 += r * w_s[k * 128 + c0 + 1];
                s2 += r * w_s[k * 128 + c0 + 2];
                s3 += r * w_s[k * 128 + c0 + 3];
            }
            __half h[4];
            h[0] = __float2half(s0); h[1] = __float2half(s1);
            h[2] = __float2half(s2); h[3] = __float2half(s3);
            *(uint2*)&g_wt[(((size_t)b * 9 + f) * COUT + oc) * CIN + c0] = *(const uint2*)h;
        }
        if (f == 0 && tid < 64) {
            float sb = 0.f;
#pragma unroll
            for (int k = 0; k < 8; k++)
                sb += r_s[tid * 8 + k] * bias[k * COUT + oc];
            g_bmix[tid * COUT + oc] = sb;
        }
        __threadfence();
        __syncthreads();
        if (tid == 0) atomicAdd(&g_mdone, 1);
        return;
    }

    if (role == 1) {
        // ================= TRANSFORM tile rj of sample rb =================
        float (*s)[33] = (float(*)[33])smem;   // [128][33]
        const int r0 = rj * 32;
        const int warp = tid >> 5, lane = tid & 31;
        {
            const int r = r0 + lane;
            const int hp = r / PADW, wp = r - hp * PADW;
            const bool ok = (r < VROWS) && (hp >= 1) && (hp < 57) && (wp >= 1) && (wp < 57);
            const int off = ok ? ((hp - 1) * WW + (wp - 1)) : 0;
            const float* xr = x + (size_t)rb * CIN * (HH * WW) + off;
#pragma unroll
            for (int k = 0; k < 16; k++) {
                const int c = warp + k * 8;
                const float v = xr[(size_t)c * (HH * WW)];
                s[c][lane] = ok ? v : 0.f;
            }
        }
        __syncthreads();
#pragma unroll
        for (int i = tid; i < 32 * 16; i += 256) {
            const int rr = i >> 4;
            const int c0 = (i & 15) * 8;
            __half h[8];
#pragma unroll
            for (int jj = 0; jj < 8; jj++)
                h[jj] = __float2half(s[c0 + jj][rr]);
            *(uint4*)&g_xt[((size_t)rb * NR2 + r0 + rr) * CIN + c0] = *(const uint4*)h;
        }
        __threadfence();
        __syncthreads();
        if (tid == 0) atomicAdd(&g_tdone[rb], 1);
        return;
    }

    // ================= CONV m-tile rj of sample rb =================
    if (tid == 0) {
        volatile int* vm = &g_mdone;
        volatile int* vt = &g_tdone[rb];
        while (*vm < MBLOCKS) __nanosleep(64);
        while (*vt < RTPS)    __nanosleep(64);
    }
    __syncthreads();
    __threadfence();

    const uint32_t sbase = smem_u32(smem);
    const int wid  = tid >> 5;
    const int lane = tid & 31;
    const int b      = rb;
    const int m_base = rj * 128;

    const int wm = (wid >> 2) * 64;          // warp m offset (2 groups)
    const int wn = (wid & 3) * 32;           // warp n offset (4 groups)
    const int gid = lane >> 2, tig = lane & 3;

    const __half* xt = g_xt + (size_t)b * NR2 * CIN;
    const __half* wt = g_wt + (size_t)b * 9 * COUT * CIN;

    float c[4][4][4];
#pragma unroll
    for (int mi = 0; mi < 4; mi++)
#pragma unroll
        for (int ni = 0; ni < 4; ni++)
#pragma unroll
            for (int k = 0; k < 4; k++) c[mi][ni][k] = 0.f;

    const int lr = tid >> 3, lj = tid & 7;

    auto load_stage = [&](int g, int s) {
        int f = g >> 1, cc = (g & 1) * 64;
        int shift = (f / 3) * PADW + (f % 3);
        const __half* gA = xt + ((size_t)(m_base + shift)) * CIN + cc;
        const __half* gB = wt + ((size_t)f * COUT) * CIN + cc;
        uint32_t sA = sbase + s * STAGE_BYTES;
        uint32_t sB = sA + 16384;
#pragma unroll
        for (int it = 0; it < 4; it++) {
            int row = lr + it * 32;
            uint32_t dchunk = (uint32_t)(lj ^ (row & 7));
            cp16(sA + row * 128 + dchunk * 16, gA + (size_t)row * CIN + lj * 8);
            cp16(sB + row * 128 + dchunk * 16, gB + (size_t)row * CIN + lj * 8);
        }
        cp_commit();
    };

    load_stage(0, 0);
    load_stage(1, 1);

    const int x7 = lane & 7;
    const int a_row = wm + (lane & 15);
    const int a_cbase = lane >> 4;
    const int b_row = wn + ((lane >> 4) << 3) + (lane & 7);
    const int b_cbase = (lane >> 3) & 1;

#pragma unroll
    for (int g = 0; g < KCH; g++) {
        if (g < KCH - 1) cp_wait<1>(); else cp_wait<0>();
        __syncthreads();
        if (g + 2 < KCH) load_stage(g + 2, (g + 2) % 3);

        const int s = g % 3;                 // compile-time after unroll
        const uint32_t sA = sbase + s * STAGE_BYTES;
        const uint32_t sB = sA + 16384;
        const uint32_t baseA = sA + (uint32_t)a_row * 128;
        const uint32_t baseB = sB + (uint32_t)b_row * 128;

#pragma unroll
        for (int ks = 0; ks < 4; ks++) {
            uint32_t a[4][4], bb[2][4];
#pragma unroll
            for (int mi = 0; mi < 4; mi++) {
                uint32_t ch = (uint32_t)((ks * 2 + a_cbase) ^ x7);
                ldsm4(a[mi], baseA + mi * 16 * 128 + ch * 16);
            }
#pragma unroll
            for (int nj = 0; nj < 2; nj++) {
                uint32_t ch = (uint32_t)((ks * 2 + b_cbase) ^ x7);
                ldsm4(bb[nj], baseB + nj * 16 * 128 + ch * 16);
            }
#pragma unroll
            for (int mi = 0; mi < 4; mi++)
#pragma unroll
                for (int ni = 0; ni < 4; ni++)
                    mma16816(c[mi][ni], a[mi], &bb[ni >> 1][(ni & 1) * 2]);
        }
    }

    // ---------------- epilogue: direct fragment -> gmem stores ----------
    const float* bm = g_bmix + b * COUT;
    float* ob = out + (size_t)b * COUT * (HH * WW);
#pragma unroll
    for (int ni = 0; ni < 4; ni++) {
        const int oc = wn + ni * 8 + 2 * tig;
        const float bv0 = __ldg(&bm[oc]);
        const float bv1 = __ldg(&bm[oc + 1]);
        float* o0 = ob + (size_t)oc * (HH * WW);
        float* o1 = o0 + (HH * WW);
#pragma unroll
        for (int mi = 0; mi < 4; mi++) {
            const int p0 = m_base + wm + mi * 16 + gid;
            const int p1 = p0 + 8;
            const int h0 = p0 / PADW, w0 = p0 - h0 * PADW;
            const int h1 = p1 / PADW, w1 = p1 - h1 * PADW;
            if (w0 < WW && h0 < HH) {
                o0[h0 * WW + w0] = c[mi][ni][0] + bv0;
                o1[h0 * WW + w0] = c[mi][ni][1] + bv1;
            }
            if (w1 < WW && h1 < HH) {
                o0[h1 * WW + w1] = c[mi][ni][2] + bv0;
                o1[h1 * WW + w1] = c[mi][ni][3] + bv1;
            }
        }
    }
}

// ---------------------------------------------------------------------------
extern "C" void kernel_launch(void* const* d_in, const int* in_sizes, int n_in,
                              void* d_out, int out_size)
{
    const float* x       = (const float*)d_in[0];   // [64,128,56,56]
    const float* routing = (const float*)d_in[1];   // [64,8]
    const float* weight  = (const float*)d_in[2];   // [8,128,128,3,3]
    const float* bias    = (const float*)d_in[3];   // [8,128]
    float* out           = (float*)d_out;           // [64,128,56,56]

    static int attr_set = 0;
    if (!attr_set) {
        cudaFuncSetAttribute(fused_kernel,
                             cudaFuncAttributeMaxDynamicSharedMemorySize, SMEM_TOTAL);
        attr_set = 1;
    }

    reset_kernel<<<1, 128>>>();
    fused_kernel<<<GRID_TOTAL, 256, SMEM_TOTAL>>>(x, routing, weight, bias, out);
}

// round 17
// speedup vs baseline: 1.2267x; 1.0995x over previous
#include <cuda_runtime.h>
#include <cuda_fp16.h>
#include <cstdint>

// ---------------------------------------------------------------------------
// Problem constants
// ---------------------------------------------------------------------------
#define BS    64
#define CIN   128
#define COUT  128
#define HH    56
#define WW    56
#define PADW  58
#define VROWS (PADW*PADW)   // 3364 meaningful padded-raster rows
#define NR2   3584          // allocated rows per sample (zero tail, zero-init)
#define RTPS  106           // ceil(3364/32) transform tiles per sample
#define MT    27            // m-tiles of 128
#define KCH   18            // 9 taps x 2 cin-chunks of 64
#define STAGE_BYTES 32768   // A tile 16KB + B tile 16KB
#define SMEM_TOTAL  (3*STAGE_BYTES)   // 96 KB

#define TBLOCKS (RTPS*BS)     // 6784 transform blocks
#define MBLOCKS (COUT*9)      // 1152 mix blocks

// ---------------------------------------------------------------------------
// Scratch (device globals; zero-initialized at load; no runtime allocation).
// Rows [3392, 3584) of each sample's g_xt slab are NEVER written — they stay
// zero from static init, which is exactly the required zero padding.
// ---------------------------------------------------------------------------
__device__ __half g_xt[(size_t)BS * NR2 * CIN];          // 58.7 MB
__device__ __half g_wt[(size_t)BS * 9 * COUT * CIN];     // 18.9 MB
__device__ float  g_bmix[BS * COUT];

// ---------------------------------------------------------------------------
// PTX helpers
// ---------------------------------------------------------------------------
__device__ __forceinline__ uint32_t smem_u32(const void* p) {
    uint32_t a;
    asm("{ .reg .u64 t; cvta.to.shared.u64 t, %1; cvt.u32.u64 %0, t; }"
        : "=r"(a) : "l"(p));
    return a;
}
__device__ __forceinline__ void cp16(uint32_t dst, const void* src) {
    asm volatile("cp.async.cg.shared.global [%0], [%1], 16;"
                 :: "r"(dst), "l"(__cvta_generic_to_global(src)) : "memory");
}
__device__ __forceinline__ void cp_commit() {
    asm volatile("cp.async.commit_group;" ::: "memory");
}
template <int N>
__device__ __forceinline__ void cp_wait() {
    asm volatile("cp.async.wait_group %0;" :: "n"(N) : "memory");
}
__device__ __forceinline__ void ldsm4(uint32_t* r, uint32_t addr) {
    asm volatile("ldmatrix.sync.aligned.m8n8.x4.shared.b16 {%0,%1,%2,%3}, [%4];"
                 : "=r"(r[0]), "=r"(r[1]), "=r"(r[2]), "=r"(r[3]) : "r"(addr));
}
__device__ __forceinline__ void mma16816(float* c, const uint32_t* a, const uint32_t* b) {
    asm volatile(
        "mma.sync.aligned.m16n8k16.row.col.f32.f16.f16.f32 "
        "{%0,%1,%2,%3}, {%4,%5,%6,%7}, {%8,%9}, {%0,%1,%2,%3};"
        : "+f"(c[0]), "+f"(c[1]), "+f"(c[2]), "+f"(c[3])
        : "r"(a[0]), "r"(a[1]), "r"(a[2]), "r"(a[3]), "r"(b[0]), "r"(b[1]));
}

// ---------------------------------------------------------------------------
// Kernel 1 (fused prologue): transform blocks [0, TBLOCKS) + mix blocks.
// ---------------------------------------------------------------------------
__global__ __launch_bounds__(256)
void prologue_kernel(const float* __restrict__ x,
                     const float* __restrict__ routing,   // [BS, 8]
                     const float* __restrict__ weight,    // [8, COUT, CIN, 3,3]
                     const float* __restrict__ bias)      // [8, COUT]
{
    __shared__ float s[128][33];
    const int blk = blockIdx.x;
    const int tid = threadIdx.x;

    if (blk < TBLOCKS) {
        const int b  = blk / RTPS;
        const int r0 = (blk - b * RTPS) * 32;
        const int warp = tid >> 5, lane = tid & 31;
        {
            const int r = r0 + lane;
            const int hp = r / PADW, wp = r - hp * PADW;
            const bool ok = (r < VROWS) && (hp >= 1) && (hp < 57) && (wp >= 1) && (wp < 57);
            const int off = ok ? ((hp - 1) * WW + (wp - 1)) : 0;
            const float* xr = x + (size_t)b * CIN * (HH * WW) + off;
#pragma unroll
            for (int k = 0; k < 16; k++) {
                const int c = warp + k * 8;
                const float v = xr[(size_t)c * (HH * WW)];
                s[c][lane] = ok ? v : 0.f;
            }
        }
        __syncthreads();
#pragma unroll
        for (int i = tid; i < 32 * 16; i += 256) {
            const int rr = i >> 4;
            const int c0 = (i & 15) * 8;
            __half h[8];
#pragma unroll
            for (int j = 0; j < 8; j++)
                h[j] = __float2half(s[c0 + j][rr]);
            *(uint4*)&g_xt[((size_t)b * NR2 + r0 + rr) * CIN + c0] = *(const uint4*)h;
        }
    } else {
        const int i2 = blk - TBLOCKS;
        const int oc = i2 & 127;
        const int f  = i2 >> 7;              // 0..8
        float* r_s = &s[0][0];               // [64][8] = 512 floats
        float* w_s = &s[16][0];              // [8][128] = 1024 floats (disjoint)

        for (int i = tid; i < 64 * 8; i += 256)
            r_s[i] = routing[i];
        for (int i = tid; i < 8 * 128; i += 256) {
            const int k = i >> 7, c = i & 127;
            w_s[k * 128 + c] = weight[(((size_t)k * COUT + oc) * CIN + c) * 9 + f];
        }
        __syncthreads();

        const int warp = tid >> 5, lane = tid & 31;
        const int c0 = lane * 4;
#pragma unroll
        for (int bi = 0; bi < 8; bi++) {
            const int b = warp + bi * 8;
            const float* rb = r_s + b * 8;
            float s0 = 0.f, s1 = 0.f, s2 = 0.f, s3 = 0.f;
#pragma unroll
            for (int k = 0; k < 8; k++) {
                const float r = rb[k];
                s0 += r * w_s[k * 128 + c0];
                s1 += r * w_s[k * 128 + c0 + 1];
                s2 += r * w_s[k * 128 + c0 + 2];
                s3 += r * w_s[k * 128 + c0 + 3];
            }
            __half h[4];
            h[0] = __float2half(s0); h[1] = __float2half(s1);
            h[2] = __float2half(s2); h[3] = __float2half(s3);
            *(uint2*)&g_wt[(((size_t)b * 9 + f) * COUT + oc) * CIN + c0] = *(const uint2*)h;
        }

        if (f == 0 && tid < 64) {
            float sb = 0.f;
#pragma unroll
            for (int k = 0; k < 8; k++)
                sb += r_s[tid * 8 + k] * bias[k * COUT + oc];
            g_bmix[tid * COUT + oc] = sb;
        }
    }
}

// ---------------------------------------------------------------------------
// Kernel 2: implicit-GEMM conv via mma.sync (HMMA). (R14 champion config)
//   CTA: 128 rows x 128 oc, 8 warps in 2(m) x 4(n), warp tile 64x32,
//   3-stage cp.async pipeline, g-loop FULLY UNROLLED, ONE sync/iter,
//   direct-store epilogue.
// ---------------------------------------------------------------------------
__global__ __launch_bounds__(256, 2)
void conv_kernel(float* __restrict__ out)
{
    extern __shared__ char smem[];
    const uint32_t sbase = smem_u32(smem);
    const int tid  = threadIdx.x;
    const int wid  = tid >> 5;
    const int lane = tid & 31;
    const int b      = blockIdx.y;
    const int m_base = blockIdx.x * 128;

    const int wm = (wid >> 2) * 64;          // warp m offset (2 groups)
    const int wn = (wid & 3) * 32;           // warp n offset (4 groups)
    const int gid = lane >> 2, tig = lane & 3;

    const __half* xt = g_xt + (size_t)b * NR2 * CIN;
    const __half* wt = g_wt + (size_t)b * 9 * COUT * CIN;

    float c[4][4][4];
#pragma unroll
    for (int mi = 0; mi < 4; mi++)
#pragma unroll
        for (int ni = 0; ni < 4; ni++)
#pragma unroll
            for (int k = 0; k < 4; k++) c[mi][ni][k] = 0.f;

    const int lr = tid >> 3, lj = tid & 7;

    auto load_stage = [&](int g, int s) {
        int f = g >> 1, cc = (g & 1) * 64;
        int shift = (f / 3) * PADW + (f % 3);
        const __half* gA = xt + ((size_t)(m_base + shift)) * CIN + cc;
        const __half* gB = wt + ((size_t)f * COUT) * CIN + cc;
        uint32_t sA = sbase + s * STAGE_BYTES;
        uint32_t sB = sA + 16384;
#pragma unroll
        for (int it = 0; it < 4; it++) {
            int row = lr + it * 32;
            uint32_t dchunk = (uint32_t)(lj ^ (row & 7));
            cp16(sA + row * 128 + dchunk * 16, gA + (size_t)row * CIN + lj * 8);
            cp16(sB + row * 128 + dchunk * 16, gB + (size_t)row * CIN + lj * 8);
        }
        cp_commit();
    };

    // prologue
    load_stage(0, 0);
    load_stage(1, 1);

    const int x7 = lane & 7;
    const int a_row = wm + (lane & 15);
    const int a_cbase = lane >> 4;
    const int b_row = wn + ((lane >> 4) << 3) + (lane & 7);
    const int b_cbase = (lane >> 3) & 1;

#pragma unroll
    for (int g = 0; g < KCH; g++) {
        if (g < KCH - 1) cp_wait<1>(); else cp_wait<0>();
        __syncthreads();
        if (g + 2 < KCH) load_stage(g + 2, (g + 2) % 3);

        const int s = g % 3;                 // compile-time after unroll
        const uint32_t sA = sbase + s * STAGE_BYTES;
        const uint32_t sB = sA + 16384;
        const uint32_t baseA = sA + (uint32_t)a_row * 128;
        const uint32_t baseB = sB + (uint32_t)b_row * 128;

#pragma unroll
        for (int ks = 0; ks < 4; ks++) {
            uint32_t a[4][4], bb[2][4];
#pragma unroll
            for (int mi = 0; mi < 4; mi++) {
                uint32_t ch = (uint32_t)((ks * 2 + a_cbase) ^ x7);
                ldsm4(a[mi], baseA + mi * 16 * 128 + ch * 16);
            }
#pragma unroll
            for (int nj = 0; nj < 2; nj++) {
                uint32_t ch = (uint32_t)((ks * 2 + b_cbase) ^ x7);
                ldsm4(bb[nj], baseB + nj * 16 * 128 + ch * 16);
            }
#pragma unroll
            for (int mi = 0; mi < 4; mi++)
#pragma unroll
                for (int ni = 0; ni < 4; ni++)
                    mma16816(c[mi][ni], a[mi], &bb[ni >> 1][(ni & 1) * 2]);
        }
        // no trailing sync: next iter's top sync orders reuse of this stage
    }

    // ---------------- epilogue: direct fragment -> gmem stores ----------
    const float* bm = g_bmix + b * COUT;
    float* ob = out + (size_t)b * COUT * (HH * WW);
#pragma unroll
    for (int ni = 0; ni < 4; ni++) {
        const int oc = wn + ni * 8 + 2 * tig;
        const float bv0 = __ldg(&bm[oc]);
        const float bv1 = __ldg(&bm[oc + 1]);
        float* o0 = ob + (size_t)oc * (HH * WW);
        float* o1 = o0 + (HH * WW);
#pragma unroll
        for (int mi = 0; mi < 4; mi++) {
            const int p0 = m_base + wm + mi * 16 + gid;
            const int p1 = p0 + 8;
            const int h0 = p0 / PADW, w0 = p0 - h0 * PADW;
            const int h1 = p1 / PADW, w1 = p1 - h1 * PADW;
            if (w0 < WW && h0 < HH) {
                o0[h0 * WW + w0] = c[mi][ni][0] + bv0;
                o1[h0 * WW + w0] = c[mi][ni][1] + bv1;
            }
            if (w1 < WW && h1 < HH) {
                o0[h1 * WW + w1] = c[mi][ni][2] + bv0;
                o1[h1 * WW + w1] = c[mi][ni][3] + bv1;
            }
        }
    }
}

// ---------------------------------------------------------------------------
extern "C" void kernel_launch(void* const* d_in, const int* in_sizes, int n_in,
                              void* d_out, int out_size)
{
    const float* x       = (const float*)d_in[0];   // [64,128,56,56]
    const float* routing = (const float*)d_in[1];   // [64,8]
    const float* weight  = (const float*)d_in[2];   // [8,128,128,3,3]
    const float* bias    = (const float*)d_in[3];   // [8,128]
    float* out           = (float*)d_out;           // [64,128,56,56]

    prologue_kernel<<<TBLOCKS + MBLOCKS, 256>>>(x, routing, weight, bias);

    static int attr_set = 0;
    if (!attr_set) {
        cudaFuncSetAttribute(conv_kernel,
                             cudaFuncAttributeMaxDynamicSharedMemorySize, SMEM_TOTAL);
        attr_set = 1;
    }
    conv_kernel<<<dim3(MT, BS), 256, SMEM_TOTAL>>>(out);
}